// round 1
// baseline (speedup 1.0000x reference)
#include <cuda_runtime.h>
#include <cuda_bf16.h>
#include <cstdint>

#define DEV_INLINE __device__ __forceinline__

// Problem constants (fixed by the dataset)
#define NSPLIT 9   // 8 splits x 256 cached keys + 1 split of 16 new keys

// -------- device scratch (no allocations allowed) --------
__device__ float g_xq[64 * 4096];                 // roped Q  [row=b*16+s][h*128+d]
__device__ float g_xk[64 * 1024];                 // roped new K [row][kv*128+d]
__device__ float g_xv[64 * 1024];                 // new V
__device__ float g_attn[64 * 4096];               // attention output pre-Wo
__device__ float g_pm[4 * 32 * 16 * NSPLIT];      // per-split row max
__device__ float g_pl[4 * 32 * 16 * NSPLIT];      // per-split row sum
__device__ float g_pacc[4 * 32 * 16 * NSPLIT * 128]; // per-split acc

DEV_INLINE uint32_t f2tf(float x) {
    uint32_t r; asm("cvt.rna.tf32.f32 %0, %1;" : "=r"(r) : "f"(x)); return r;
}

DEV_INLINE void mma_tf32(float* c, const uint32_t* a, const uint32_t* b) {
    asm volatile(
        "mma.sync.aligned.m16n8k8.row.col.f32.tf32.tf32.f32 "
        "{%0,%1,%2,%3}, {%4,%5,%6,%7}, {%8,%9}, {%0,%1,%2,%3};\n"
        : "+f"(c[0]), "+f"(c[1]), "+f"(c[2]), "+f"(c[3])
        : "r"(a[0]), "r"(a[1]), "r"(a[2]), "r"(a[3]), "r"(b[0]), "r"(b[1]));
}

// ============================================================
// Kernel 1: fused QKV projection + RoPE.
// C[64 x 6144] = x[64x4096] @ [Wq|Wk|Wv]. Each block: 64 rows x 32 cols.
// 4 warps, warp w = rows 16w..16w+15 (warp == batch index b).
// ============================================================
__global__ __launch_bounds__(128) void qkv_kernel(
    const float* __restrict__ x, const float* __restrict__ Wq,
    const float* __restrict__ Wk, const float* __restrict__ Wv,
    const float* __restrict__ fc, const float* __restrict__ fs) {
    const int n0 = blockIdx.x * 32;
    const float* Bp; int ldn, nb;
    if (n0 < 4096)      { Bp = Wq; ldn = 4096; nb = n0; }
    else if (n0 < 5120) { Bp = Wk; ldn = 1024; nb = n0 - 4096; }
    else                { Bp = Wv; ldn = 1024; nb = n0 - 5120; }

    __shared__ uint32_t As[64][36];   // A tile [row][k], pad 36 => conflict-free frags
    __shared__ uint32_t Bs[32][40];   // B tile [k][n],   pad 40 => conflict-free frags

    const int tid = threadIdx.x, w = tid >> 5, lane = tid & 31;
    const int g = lane >> 2, tg = lane & 3;

    float acc[4][4];
#pragma unroll
    for (int i = 0; i < 4; i++)
#pragma unroll
        for (int j = 0; j < 4; j++) acc[i][j] = 0.f;

    for (int kc = 0; kc < 4096; kc += 32) {
#pragma unroll
        for (int i = 0; i < 4; i++) {
            int idx = tid + i * 128; int r = idx >> 3, c = (idx & 7) * 4;
            float4 v = *(const float4*)(x + r * 4096 + kc + c);
            As[r][c] = f2tf(v.x); As[r][c + 1] = f2tf(v.y);
            As[r][c + 2] = f2tf(v.z); As[r][c + 3] = f2tf(v.w);
        }
#pragma unroll
        for (int i = 0; i < 2; i++) {
            int idx = tid + i * 128; int r = idx >> 3, c = (idx & 7) * 4;
            float4 v = *(const float4*)(Bp + (kc + r) * ldn + nb + c);
            Bs[r][c] = f2tf(v.x); Bs[r][c + 1] = f2tf(v.y);
            Bs[r][c + 2] = f2tf(v.z); Bs[r][c + 3] = f2tf(v.w);
        }
        __syncthreads();
#pragma unroll
        for (int ks = 0; ks < 4; ks++) {
            uint32_t a[4];
            a[0] = As[w * 16 + g][ks * 8 + tg];
            a[1] = As[w * 16 + g + 8][ks * 8 + tg];
            a[2] = As[w * 16 + g][ks * 8 + tg + 4];
            a[3] = As[w * 16 + g + 8][ks * 8 + tg + 4];
#pragma unroll
            for (int nt = 0; nt < 4; nt++) {
                uint32_t bb[2];
                bb[0] = Bs[ks * 8 + tg][nt * 8 + g];
                bb[1] = Bs[ks * 8 + tg + 4][nt * 8 + g];
                mma_tf32(acc[nt], a, bb);
            }
        }
        __syncthreads();
    }

    // Epilogue: thread owns (row rA, cols col,col+1) and (row rB, cols col,col+1)
    const int rA = w * 16 + g, rB = rA + 8;
    const int sA = rA & 15, sB = rB & 15;   // token position within the 16 new
#pragma unroll
    for (int nt = 0; nt < 4; nt++) {
        int n = n0 + nt * 8 + tg * 2;
        if (n < 4096) {            // Q + RoPE (interleaved pairs)
            int i2 = (n & 127) >> 1;
            float cA = fc[sA * 64 + i2], snA = fs[sA * 64 + i2];
            float cB = fc[sB * 64 + i2], snB = fs[sB * 64 + i2];
            g_xq[rA * 4096 + n]     = acc[nt][0] * cA - acc[nt][1] * snA;
            g_xq[rA * 4096 + n + 1] = acc[nt][0] * snA + acc[nt][1] * cA;
            g_xq[rB * 4096 + n]     = acc[nt][2] * cB - acc[nt][3] * snB;
            g_xq[rB * 4096 + n + 1] = acc[nt][2] * snB + acc[nt][3] * cB;
        } else if (n < 5120) {     // K + RoPE
            int nk = n - 4096; int i2 = (nk & 127) >> 1;
            float cA = fc[sA * 64 + i2], snA = fs[sA * 64 + i2];
            float cB = fc[sB * 64 + i2], snB = fs[sB * 64 + i2];
            g_xk[rA * 1024 + nk]     = acc[nt][0] * cA - acc[nt][1] * snA;
            g_xk[rA * 1024 + nk + 1] = acc[nt][0] * snA + acc[nt][1] * cA;
            g_xk[rB * 1024 + nk]     = acc[nt][2] * cB - acc[nt][3] * snB;
            g_xk[rB * 1024 + nk + 1] = acc[nt][2] * snB + acc[nt][3] * cB;
        } else {                   // V (no RoPE)
            int nv = n - 5120;
            g_xv[rA * 1024 + nv]     = acc[nt][0];
            g_xv[rA * 1024 + nv + 1] = acc[nt][1];
            g_xv[rB * 1024 + nv]     = acc[nt][2];
            g_xv[rB * 1024 + nv + 1] = acc[nt][3];
        }
    }
}

// ============================================================
// Kernel 2: split-KV flash attention.
// grid (split, kvh, b). Block = 64 q-rows (4 heads x 16 tokens) vs its key split.
// splits 0..7: 256 cached keys each; split 8: the 16 new keys from scratch.
// ============================================================
#define QLD 132
#define KLD 132
#define VLD 136
#define PLD 68
#define ATTN_SMEM ((64 * QLD + 64 * KLD + 64 * VLD + 4 * 16 * PLD) * 4)

__global__ __launch_bounds__(128) void attn_kernel(
    const float* __restrict__ cache_k, const float* __restrict__ cache_v) {
    extern __shared__ uint32_t sm[];
    uint32_t* Qs = sm;
    uint32_t* Ks = Qs + 64 * QLD;
    uint32_t* Vs = Ks + 64 * KLD;
    uint32_t* Ps = Vs + 64 * VLD;

    const int split = blockIdx.x, kvh = blockIdx.y, b = blockIdx.z;
    const int tid = threadIdx.x, w = tid >> 5, lane = tid & 31;
    const int g = lane >> 2, tg = lane & 3;

    // Load Q tile [64 x 128] as tf32
#pragma unroll
    for (int i = 0; i < 16; i++) {
        int idx = tid + i * 128; int r = idx >> 5, c = (idx & 31) * 4;
        int hig = r >> 4, s = r & 15;
        float4 v = *(const float4*)(g_xq + (b * 16 + s) * 4096 + (kvh * 4 + hig) * 128 + c);
        uint32_t* q = &Qs[r * QLD + c];
        q[0] = f2tf(v.x); q[1] = f2tf(v.y); q[2] = f2tf(v.z); q[3] = f2tf(v.w);
    }

    float acc[16][4];
#pragma unroll
    for (int i = 0; i < 16; i++)
#pragma unroll
        for (int j = 0; j < 4; j++) acc[i][j] = 0.f;
    float m0 = -1e30f, m1 = -1e30f, l0 = 0.f, l1 = 0.f;
    const int nch = (split < 8) ? 4 : 1;
    const float scale = 0.08838834764831845f;   // 1/sqrt(128)

    for (int ch = 0; ch < nch; ch++) {
        // Load K/V chunk (64 keys x 128)
#pragma unroll
        for (int i = 0; i < 16; i++) {
            int idx = tid + i * 128; int jk = idx >> 5, c = (idx & 31) * 4;
            float4 kv4, vv4;
            if (split < 8) {
                int j = split * 256 + ch * 64 + jk;           // always < 2048
                int off = ((b * 4096 + j) * 8 + kvh) * 128 + c;
                kv4 = *(const float4*)(cache_k + off);
                vv4 = *(const float4*)(cache_v + off);
            } else if (jk < 16) {
                int off = (b * 16 + jk) * 1024 + kvh * 128 + c;
                kv4 = *(const float4*)(g_xk + off);
                vv4 = *(const float4*)(g_xv + off);
            } else {
                kv4 = make_float4(0.f, 0.f, 0.f, 0.f); vv4 = kv4;
            }
            uint32_t* kd = &Ks[jk * KLD + c];
            kd[0] = f2tf(kv4.x); kd[1] = f2tf(kv4.y); kd[2] = f2tf(kv4.z); kd[3] = f2tf(kv4.w);
            uint32_t* vd = &Vs[jk * VLD + c];
            vd[0] = f2tf(vv4.x); vd[1] = f2tf(vv4.y); vd[2] = f2tf(vv4.z); vd[3] = f2tf(vv4.w);
        }
        __syncthreads();

        // GEMM1: S[16x64 per warp] = Q @ K^T   (contraction over d=128)
        float sc[8][4];
#pragma unroll
        for (int i = 0; i < 8; i++)
#pragma unroll
            for (int j = 0; j < 4; j++) sc[i][j] = 0.f;
#pragma unroll
        for (int ks = 0; ks < 16; ks++) {
            uint32_t a[4];
            a[0] = Qs[(w * 16 + g) * QLD + ks * 8 + tg];
            a[1] = Qs[(w * 16 + g + 8) * QLD + ks * 8 + tg];
            a[2] = Qs[(w * 16 + g) * QLD + ks * 8 + tg + 4];
            a[3] = Qs[(w * 16 + g + 8) * QLD + ks * 8 + tg + 4];
#pragma unroll
            for (int nt = 0; nt < 8; nt++) {
                uint32_t bb[2];
                bb[0] = Ks[(nt * 8 + g) * KLD + ks * 8 + tg];
                bb[1] = Ks[(nt * 8 + g) * KLD + ks * 8 + tg + 4];
                mma_tf32(sc[nt], a, bb);
            }
        }

        // scale + mask + online softmax
        float mx0 = -1e30f, mx1 = -1e30f;
#pragma unroll
        for (int nt = 0; nt < 8; nt++) {
#pragma unroll
            for (int r = 0; r < 4; r++) {
                float v = sc[nt][r] * scale;
                if (split == 8) {
                    int key = nt * 8 + tg * 2 + (r & 1);
                    if (key >= 16) v = -1e30f;
                }
                sc[nt][r] = v;
            }
            mx0 = fmaxf(mx0, fmaxf(sc[nt][0], sc[nt][1]));
            mx1 = fmaxf(mx1, fmaxf(sc[nt][2], sc[nt][3]));
        }
        mx0 = fmaxf(mx0, __shfl_xor_sync(0xffffffffu, mx0, 1));
        mx0 = fmaxf(mx0, __shfl_xor_sync(0xffffffffu, mx0, 2));
        mx1 = fmaxf(mx1, __shfl_xor_sync(0xffffffffu, mx1, 1));
        mx1 = fmaxf(mx1, __shfl_xor_sync(0xffffffffu, mx1, 2));
        float nm0 = fmaxf(m0, mx0), nm1 = fmaxf(m1, mx1);
        float f0 = __expf(m0 - nm0), f1 = __expf(m1 - nm1);
        float s0 = 0.f, s1 = 0.f;
#pragma unroll
        for (int nt = 0; nt < 8; nt++) {
            float p0 = __expf(sc[nt][0] - nm0), p1 = __expf(sc[nt][1] - nm0);
            float p2 = __expf(sc[nt][2] - nm1), p3 = __expf(sc[nt][3] - nm1);
            s0 += p0 + p1; s1 += p2 + p3;
            uint32_t* pr  = &Ps[(w * 16 + g) * PLD + nt * 8 + tg * 2];
            pr[0] = f2tf(p0); pr[1] = f2tf(p1);
            uint32_t* pr2 = &Ps[(w * 16 + g + 8) * PLD + nt * 8 + tg * 2];
            pr2[0] = f2tf(p2); pr2[1] = f2tf(p3);
        }
        s0 += __shfl_xor_sync(0xffffffffu, s0, 1);
        s0 += __shfl_xor_sync(0xffffffffu, s0, 2);
        s1 += __shfl_xor_sync(0xffffffffu, s1, 1);
        s1 += __shfl_xor_sync(0xffffffffu, s1, 2);
        l0 = l0 * f0 + s0; l1 = l1 * f1 + s1;
        m0 = nm0; m1 = nm1;
#pragma unroll
        for (int nt = 0; nt < 16; nt++) {
            acc[nt][0] *= f0; acc[nt][1] *= f0;
            acc[nt][2] *= f1; acc[nt][3] *= f1;
        }
        __syncwarp();

        // GEMM2: acc[16x128 per warp] += P @ V (contraction over 64 keys)
#pragma unroll
        for (int k2 = 0; k2 < 8; k2++) {
            uint32_t a[4];
            a[0] = Ps[(w * 16 + g) * PLD + k2 * 8 + tg];
            a[1] = Ps[(w * 16 + g + 8) * PLD + k2 * 8 + tg];
            a[2] = Ps[(w * 16 + g) * PLD + k2 * 8 + tg + 4];
            a[3] = Ps[(w * 16 + g + 8) * PLD + k2 * 8 + tg + 4];
#pragma unroll
            for (int nt = 0; nt < 16; nt++) {
                uint32_t bb[2];
                bb[0] = Vs[(k2 * 8 + tg) * VLD + nt * 8 + g];
                bb[1] = Vs[(k2 * 8 + tg + 4) * VLD + nt * 8 + g];
                mma_tf32(acc[nt], a, bb);
            }
        }
        __syncthreads();
    }

    // write split partials
    const int h = kvh * 4 + w;
    const int baseA = ((b * 32 + h) * 16 + g) * NSPLIT + split;
    const int baseB = ((b * 32 + h) * 16 + g + 8) * NSPLIT + split;
    if (tg == 0) {
        g_pm[baseA] = m0; g_pl[baseA] = l0;
        g_pm[baseB] = m1; g_pl[baseB] = l1;
    }
#pragma unroll
    for (int nt = 0; nt < 16; nt++) {
        int col = nt * 8 + tg * 2;
        g_pacc[baseA * 128 + col]     = acc[nt][0];
        g_pacc[baseA * 128 + col + 1] = acc[nt][1];
        g_pacc[baseB * 128 + col]     = acc[nt][2];
        g_pacc[baseB * 128 + col + 1] = acc[nt][3];
    }
}

// ============================================================
// Kernel 3: combine the 9 splits (numerically exact merge)
// ============================================================
__global__ __launch_bounds__(128) void combine_kernel() {
    int bhs = blockIdx.x;          // 0..2047 = ((b*32+h)*16+s)
    int d = threadIdx.x;
    int base = bhs * NSPLIT;
    float m = -1e30f;
#pragma unroll
    for (int i = 0; i < NSPLIT; i++) m = fmaxf(m, g_pm[base + i]);
    float L = 0.f, o = 0.f;
#pragma unroll
    for (int i = 0; i < NSPLIT; i++) {
        float e = __expf(g_pm[base + i] - m);
        L += g_pl[base + i] * e;
        o += g_pacc[(base + i) * 128 + d] * e;
    }
    int b = bhs >> 9, h = (bhs >> 4) & 31, s = bhs & 15;
    g_attn[(b * 16 + s) * 4096 + h * 128 + d] = o / L;
}

// ============================================================
// Kernel 4: output projection  out[64x4096] = attn @ Wo
// ============================================================
__global__ __launch_bounds__(128) void out_kernel(
    const float* __restrict__ Wo, float* __restrict__ out) {
    const int n0 = blockIdx.x * 32;
    __shared__ uint32_t As[64][36];
    __shared__ uint32_t Bs[32][40];
    const int tid = threadIdx.x, w = tid >> 5, lane = tid & 31;
    const int g = lane >> 2, tg = lane & 3;

    float acc[4][4];
#pragma unroll
    for (int i = 0; i < 4; i++)
#pragma unroll
        for (int j = 0; j < 4; j++) acc[i][j] = 0.f;

    for (int kc = 0; kc < 4096; kc += 32) {
#pragma unroll
        for (int i = 0; i < 4; i++) {
            int idx = tid + i * 128; int r = idx >> 3, c = (idx & 7) * 4;
            float4 v = *(const float4*)(g_attn + r * 4096 + kc + c);
            As[r][c] = f2tf(v.x); As[r][c + 1] = f2tf(v.y);
            As[r][c + 2] = f2tf(v.z); As[r][c + 3] = f2tf(v.w);
        }
#pragma unroll
        for (int i = 0; i < 2; i++) {
            int idx = tid + i * 128; int r = idx >> 3, c = (idx & 7) * 4;
            float4 v = *(const float4*)(Wo + (kc + r) * 4096 + n0 + c);
            Bs[r][c] = f2tf(v.x); Bs[r][c + 1] = f2tf(v.y);
            Bs[r][c + 2] = f2tf(v.z); Bs[r][c + 3] = f2tf(v.w);
        }
        __syncthreads();
#pragma unroll
        for (int ks = 0; ks < 4; ks++) {
            uint32_t a[4];
            a[0] = As[w * 16 + g][ks * 8 + tg];
            a[1] = As[w * 16 + g + 8][ks * 8 + tg];
            a[2] = As[w * 16 + g][ks * 8 + tg + 4];
            a[3] = As[w * 16 + g + 8][ks * 8 + tg + 4];
#pragma unroll
            for (int nt = 0; nt < 4; nt++) {
                uint32_t bb[2];
                bb[0] = Bs[ks * 8 + tg][nt * 8 + g];
                bb[1] = Bs[ks * 8 + tg + 4][nt * 8 + g];
                mma_tf32(acc[nt], a, bb);
            }
        }
        __syncthreads();
    }

    const int rA = w * 16 + g, rB = rA + 8;
#pragma unroll
    for (int nt = 0; nt < 4; nt++) {
        int n = n0 + nt * 8 + tg * 2;
        out[rA * 4096 + n]     = acc[nt][0];
        out[rA * 4096 + n + 1] = acc[nt][1];
        out[rB * 4096 + n]     = acc[nt][2];
        out[rB * 4096 + n + 1] = acc[nt][3];
    }
}

// ============================================================
extern "C" void kernel_launch(void* const* d_in, const int* in_sizes, int n_in,
                              void* d_out, int out_size) {
    const float* x  = (const float*)d_in[0];
    const float* fc = (const float*)d_in[1];
    const float* fs = (const float*)d_in[2];
    const float* ck = (const float*)d_in[3];
    const float* cv = (const float*)d_in[4];
    const float* Wq = (const float*)d_in[5];
    const float* Wk = (const float*)d_in[6];
    const float* Wv = (const float*)d_in[7];
    const float* Wo = (const float*)d_in[8];
    float* out = (float*)d_out;

    cudaFuncSetAttribute(attn_kernel, cudaFuncAttributeMaxDynamicSharedMemorySize, ATTN_SMEM);

    qkv_kernel<<<192, 128>>>(x, Wq, Wk, Wv, fc, fs);
    attn_kernel<<<dim3(NSPLIT, 8, 4), 128, ATTN_SMEM>>>(ck, cv);
    combine_kernel<<<2048, 128>>>();
    out_kernel<<<128, 128>>>(Wo, out);
}

// round 2
// speedup vs baseline: 3.1590x; 3.1590x over previous
#include <cuda_runtime.h>
#include <cuda_bf16.h>
#include <cstdint>

#define DEV_INLINE __device__ __forceinline__

#define NSPLIT 9      // attention KV splits: 8 x 256 cached + 1 x 16 new
#define KSPLIT 8      // GEMM K splits
#define KCH    512    // K per split
#define BN     128    // N tile
#define ALD    36     // A smem ld (words)
#define BLD    136    // B smem ld (words)
#define STAGE_A (64 * ALD)
#define STAGE_B (32 * BLD)
#define STAGE_W (STAGE_A + STAGE_B)
#define GEMM_SMEM (3 * STAGE_W * 4)

// -------- device scratch (no allocations allowed) --------
__device__ float g_xq[64 * 4096];
__device__ float g_xk[64 * 1024];
__device__ float g_xv[64 * 1024];
__device__ float g_attn[64 * 4096];
__device__ float g_part[KSPLIT * 64 * 6144];          // split-K partials (reused)
__device__ float g_pm[4 * 32 * 16 * NSPLIT];
__device__ float g_pl[4 * 32 * 16 * NSPLIT];
__device__ float g_pacc[4 * 32 * 16 * NSPLIT * 128];

DEV_INLINE uint32_t f2tf(float x) {
    uint32_t r; asm("cvt.rna.tf32.f32 %0, %1;" : "=r"(r) : "f"(x)); return r;
}
DEV_INLINE uint32_t smem_u32(const void* p) {
    uint32_t a;
    asm("{ .reg .u64 t; cvta.to.shared.u64 t, %1; cvt.u32.u64 %0, t; }" : "=r"(a) : "l"(p));
    return a;
}
DEV_INLINE void mma_tf32(float* c, const uint32_t* a, const uint32_t* b) {
    asm volatile(
        "mma.sync.aligned.m16n8k8.row.col.f32.tf32.tf32.f32 "
        "{%0,%1,%2,%3}, {%4,%5,%6,%7}, {%8,%9}, {%0,%1,%2,%3};\n"
        : "+f"(c[0]), "+f"(c[1]), "+f"(c[2]), "+f"(c[3])
        : "r"(a[0]), "r"(a[1]), "r"(a[2]), "r"(a[3]), "r"(b[0]), "r"(b[1]));
}
DEV_INLINE void cp16(uint32_t dst, const float* src) {
    asm volatile("cp.async.cg.shared.global [%0], [%1], 16;\n" :: "r"(dst), "l"(src));
}

// ============================================================
// Split-K GEMM: C_part[split][64 x NTOT] = A[64 x Kchunk] @ B
// Block = 64 x 128 tile, 256 threads (8 warps), 3-stage cp.async.
// ============================================================
template<int NTOT, bool AFA>
__global__ __launch_bounds__(256) void gemm_k(
    const float* __restrict__ Ain, const float* __restrict__ W0,
    const float* __restrict__ W1, const float* __restrict__ W2) {
    extern __shared__ float sm[];
    const int ntile = blockIdx.x, split = blockIdx.y;
    const int n0 = ntile * BN;
    const float* A = AFA ? (const float*)g_attn : Ain;
    const float* Bp; int ldn, nb;
    if (NTOT == 4096) { Bp = W0; ldn = 4096; nb = n0; }
    else {
        if (n0 < 4096)      { Bp = W0; ldn = 4096; nb = n0; }
        else if (n0 < 5120) { Bp = W1; ldn = 1024; nb = n0 - 4096; }
        else                { Bp = W2; ldn = 1024; nb = n0 - 5120; }
    }
    const int k0 = split * KCH;
    const int tid = threadIdx.x;
    const uint32_t sbase = smem_u32(sm);

    auto issue = [&](int it, int buf) {
        const int kc = k0 + it * 32;
        uint32_t as_ = sbase + buf * STAGE_W * 4;
        uint32_t bs_ = as_ + STAGE_A * 4;
#pragma unroll
        for (int i = 0; i < 2; i++) {                 // A: 64x32 = 512 float4
            int idx = tid + i * 256; int r = idx >> 3, c = (idx & 7) * 4;
            cp16(as_ + (r * ALD + c) * 4, A + r * 4096 + kc + c);
        }
#pragma unroll
        for (int i = 0; i < 4; i++) {                 // B: 32x128 = 1024 float4
            int idx = tid + i * 256; int r = idx >> 5, c = (idx & 31) * 4;
            cp16(bs_ + (r * BLD + c) * 4, Bp + (kc + r) * ldn + nb + c);
        }
        asm volatile("cp.async.commit_group;\n");
    };

    const int w = tid >> 5, lane = tid & 31, g = lane >> 2, tg = lane & 3;
    const int mw = (w & 3) * 16;
    const int nw = (w >> 2) * 64;

    float acc[8][4];
#pragma unroll
    for (int i = 0; i < 8; i++)
#pragma unroll
        for (int j = 0; j < 4; j++) acc[i][j] = 0.f;

    issue(0, 0); issue(1, 1);

    for (int it = 0; it < 16; it++) {
        __syncthreads();                  // all warps done reading buf (it+2)%3
        if (it + 2 < 16) issue(it + 2, (it + 2) % 3);
        else asm volatile("cp.async.commit_group;\n");   // keep group count aligned
        asm volatile("cp.async.wait_group 2;\n");        // stage 'it' complete
        __syncthreads();
        const float* As = sm + (it % 3) * STAGE_W;
        const float* Bs = As + STAGE_A;
#pragma unroll
        for (int ks = 0; ks < 4; ks++) {
            const int kk = ks * 8;
            uint32_t a[4];
            a[0] = f2tf(As[(mw + g) * ALD + kk + tg]);
            a[1] = f2tf(As[(mw + g + 8) * ALD + kk + tg]);
            a[2] = f2tf(As[(mw + g) * ALD + kk + tg + 4]);
            a[3] = f2tf(As[(mw + g + 8) * ALD + kk + tg + 4]);
#pragma unroll
            for (int nt = 0; nt < 8; nt++) {
                uint32_t bb[2];
                bb[0] = f2tf(Bs[(kk + tg) * BLD + nw + nt * 8 + g]);
                bb[1] = f2tf(Bs[(kk + tg + 4) * BLD + nw + nt * 8 + g]);
                mma_tf32(acc[nt], a, bb);
            }
        }
    }

    float* outp = g_part + (size_t)split * 64 * NTOT;
#pragma unroll
    for (int nt = 0; nt < 8; nt++) {
        int col = n0 + nw + nt * 8 + tg * 2;
        outp[(mw + g) * NTOT + col]         = acc[nt][0];
        outp[(mw + g) * NTOT + col + 1]     = acc[nt][1];
        outp[(mw + g + 8) * NTOT + col]     = acc[nt][2];
        outp[(mw + g + 8) * NTOT + col + 1] = acc[nt][3];
    }
}

// ============================================================
// qkv reduce: sum 8 split partials + RoPE + scatter to g_xq/g_xk/g_xv
// ============================================================
__global__ __launch_bounds__(256) void qkv_reduce(
    const float* __restrict__ fc, const float* __restrict__ fs) {
    int idx = blockIdx.x * 256 + threadIdx.x;       // 64*3072 pairs
    int r = idx / 3072, p = idx % 3072;
    int n = p * 2;
    float v0 = 0.f, v1 = 0.f;
#pragma unroll
    for (int s = 0; s < 8; s++) {
        float2 vv = *(const float2*)(g_part + ((size_t)s * 64 + r) * 6144 + n);
        v0 += vv.x; v1 += vv.y;
    }
    int srow = r & 15;
    if (n < 4096) {
        int i2 = (n & 127) >> 1;
        float c = fc[srow * 64 + i2], sn = fs[srow * 64 + i2];
        g_xq[r * 4096 + n]     = v0 * c - v1 * sn;
        g_xq[r * 4096 + n + 1] = v0 * sn + v1 * c;
    } else if (n < 5120) {
        int nk = n - 4096; int i2 = (nk & 127) >> 1;
        float c = fc[srow * 64 + i2], sn = fs[srow * 64 + i2];
        g_xk[r * 1024 + nk]     = v0 * c - v1 * sn;
        g_xk[r * 1024 + nk + 1] = v0 * sn + v1 * c;
    } else {
        int nv = n - 5120;
        g_xv[r * 1024 + nv]     = v0;
        g_xv[r * 1024 + nv + 1] = v1;
    }
}

// ============================================================
// out reduce: sum 8 split partials -> final output
// ============================================================
__global__ __launch_bounds__(256) void out_reduce(float* __restrict__ out) {
    int idx = blockIdx.x * 256 + threadIdx.x;       // 64*1024 float4s
    float4 acc = make_float4(0.f, 0.f, 0.f, 0.f);
#pragma unroll
    for (int s = 0; s < 8; s++) {
        float4 v = *(const float4*)(g_part + (size_t)s * 64 * 4096 + idx * 4);
        acc.x += v.x; acc.y += v.y; acc.z += v.z; acc.w += v.w;
    }
    *(float4*)(out + idx * 4) = acc;
}

// ============================================================
// split-KV flash attention (unchanged from R1 — validated)
// ============================================================
#define QLD 132
#define KLD 132
#define VLD 136
#define PLD 68
#define ATTN_SMEM ((64 * QLD + 64 * KLD + 64 * VLD + 4 * 16 * PLD) * 4)

__global__ __launch_bounds__(128) void attn_kernel(
    const float* __restrict__ cache_k, const float* __restrict__ cache_v) {
    extern __shared__ uint32_t smu[];
    uint32_t* Qs = smu;
    uint32_t* Ks = Qs + 64 * QLD;
    uint32_t* Vs = Ks + 64 * KLD;
    uint32_t* Ps = Vs + 64 * VLD;

    const int split = blockIdx.x, kvh = blockIdx.y, b = blockIdx.z;
    const int tid = threadIdx.x, w = tid >> 5, lane = tid & 31;
    const int g = lane >> 2, tg = lane & 3;

#pragma unroll
    for (int i = 0; i < 16; i++) {
        int idx = tid + i * 128; int r = idx >> 5, c = (idx & 31) * 4;
        int hig = r >> 4, s = r & 15;
        float4 v = *(const float4*)(g_xq + (b * 16 + s) * 4096 + (kvh * 4 + hig) * 128 + c);
        uint32_t* q = &Qs[r * QLD + c];
        q[0] = f2tf(v.x); q[1] = f2tf(v.y); q[2] = f2tf(v.z); q[3] = f2tf(v.w);
    }

    float acc[16][4];
#pragma unroll
    for (int i = 0; i < 16; i++)
#pragma unroll
        for (int j = 0; j < 4; j++) acc[i][j] = 0.f;
    float m0 = -1e30f, m1 = -1e30f, l0 = 0.f, l1 = 0.f;
    const int nch = (split < 8) ? 4 : 1;
    const float scale = 0.08838834764831845f;

    for (int ch = 0; ch < nch; ch++) {
#pragma unroll
        for (int i = 0; i < 16; i++) {
            int idx = tid + i * 128; int jk = idx >> 5, c = (idx & 31) * 4;
            float4 kv4, vv4;
            if (split < 8) {
                int j = split * 256 + ch * 64 + jk;
                int off = ((b * 4096 + j) * 8 + kvh) * 128 + c;
                kv4 = *(const float4*)(cache_k + off);
                vv4 = *(const float4*)(cache_v + off);
            } else if (jk < 16) {
                int off = (b * 16 + jk) * 1024 + kvh * 128 + c;
                kv4 = *(const float4*)(g_xk + off);
                vv4 = *(const float4*)(g_xv + off);
            } else {
                kv4 = make_float4(0.f, 0.f, 0.f, 0.f); vv4 = kv4;
            }
            uint32_t* kd = &Ks[jk * KLD + c];
            kd[0] = f2tf(kv4.x); kd[1] = f2tf(kv4.y); kd[2] = f2tf(kv4.z); kd[3] = f2tf(kv4.w);
            uint32_t* vd = &Vs[jk * VLD + c];
            vd[0] = f2tf(vv4.x); vd[1] = f2tf(vv4.y); vd[2] = f2tf(vv4.z); vd[3] = f2tf(vv4.w);
        }
        __syncthreads();

        float sc[8][4];
#pragma unroll
        for (int i = 0; i < 8; i++)
#pragma unroll
            for (int j = 0; j < 4; j++) sc[i][j] = 0.f;
#pragma unroll
        for (int ks = 0; ks < 16; ks++) {
            uint32_t a[4];
            a[0] = Qs[(w * 16 + g) * QLD + ks * 8 + tg];
            a[1] = Qs[(w * 16 + g + 8) * QLD + ks * 8 + tg];
            a[2] = Qs[(w * 16 + g) * QLD + ks * 8 + tg + 4];
            a[3] = Qs[(w * 16 + g + 8) * QLD + ks * 8 + tg + 4];
#pragma unroll
            for (int nt = 0; nt < 8; nt++) {
                uint32_t bb[2];
                bb[0] = Ks[(nt * 8 + g) * KLD + ks * 8 + tg];
                bb[1] = Ks[(nt * 8 + g) * KLD + ks * 8 + tg + 4];
                mma_tf32(sc[nt], a, bb);
            }
        }

        float mx0 = -1e30f, mx1 = -1e30f;
#pragma unroll
        for (int nt = 0; nt < 8; nt++) {
#pragma unroll
            for (int r = 0; r < 4; r++) {
                float v = sc[nt][r] * scale;
                if (split == 8) {
                    int key = nt * 8 + tg * 2 + (r & 1);
                    if (key >= 16) v = -1e30f;
                }
                sc[nt][r] = v;
            }
            mx0 = fmaxf(mx0, fmaxf(sc[nt][0], sc[nt][1]));
            mx1 = fmaxf(mx1, fmaxf(sc[nt][2], sc[nt][3]));
        }
        mx0 = fmaxf(mx0, __shfl_xor_sync(0xffffffffu, mx0, 1));
        mx0 = fmaxf(mx0, __shfl_xor_sync(0xffffffffu, mx0, 2));
        mx1 = fmaxf(mx1, __shfl_xor_sync(0xffffffffu, mx1, 1));
        mx1 = fmaxf(mx1, __shfl_xor_sync(0xffffffffu, mx1, 2));
        float nm0 = fmaxf(m0, mx0), nm1 = fmaxf(m1, mx1);
        float f0 = __expf(m0 - nm0), f1 = __expf(m1 - nm1);
        float s0 = 0.f, s1 = 0.f;
#pragma unroll
        for (int nt = 0; nt < 8; nt++) {
            float p0 = __expf(sc[nt][0] - nm0), p1 = __expf(sc[nt][1] - nm0);
            float p2 = __expf(sc[nt][2] - nm1), p3 = __expf(sc[nt][3] - nm1);
            s0 += p0 + p1; s1 += p2 + p3;
            uint32_t* pr  = &Ps[(w * 16 + g) * PLD + nt * 8 + tg * 2];
            pr[0] = f2tf(p0); pr[1] = f2tf(p1);
            uint32_t* pr2 = &Ps[(w * 16 + g + 8) * PLD + nt * 8 + tg * 2];
            pr2[0] = f2tf(p2); pr2[1] = f2tf(p3);
        }
        s0 += __shfl_xor_sync(0xffffffffu, s0, 1);
        s0 += __shfl_xor_sync(0xffffffffu, s0, 2);
        s1 += __shfl_xor_sync(0xffffffffu, s1, 1);
        s1 += __shfl_xor_sync(0xffffffffu, s1, 2);
        l0 = l0 * f0 + s0; l1 = l1 * f1 + s1;
        m0 = nm0; m1 = nm1;
#pragma unroll
        for (int nt = 0; nt < 16; nt++) {
            acc[nt][0] *= f0; acc[nt][1] *= f0;
            acc[nt][2] *= f1; acc[nt][3] *= f1;
        }
        __syncwarp();

#pragma unroll
        for (int k2 = 0; k2 < 8; k2++) {
            uint32_t a[4];
            a[0] = Ps[(w * 16 + g) * PLD + k2 * 8 + tg];
            a[1] = Ps[(w * 16 + g + 8) * PLD + k2 * 8 + tg];
            a[2] = Ps[(w * 16 + g) * PLD + k2 * 8 + tg + 4];
            a[3] = Ps[(w * 16 + g + 8) * PLD + k2 * 8 + tg + 4];
#pragma unroll
            for (int nt = 0; nt < 16; nt++) {
                uint32_t bb[2];
                bb[0] = Vs[(k2 * 8 + tg) * VLD + nt * 8 + g];
                bb[1] = Vs[(k2 * 8 + tg + 4) * VLD + nt * 8 + g];
                mma_tf32(acc[nt], a, bb);
            }
        }
        __syncthreads();
    }

    const int h = kvh * 4 + w;
    const int baseA = ((b * 32 + h) * 16 + g) * NSPLIT + split;
    const int baseB = ((b * 32 + h) * 16 + g + 8) * NSPLIT + split;
    if (tg == 0) {
        g_pm[baseA] = m0; g_pl[baseA] = l0;
        g_pm[baseB] = m1; g_pl[baseB] = l1;
    }
#pragma unroll
    for (int nt = 0; nt < 16; nt++) {
        int col = nt * 8 + tg * 2;
        g_pacc[baseA * 128 + col]     = acc[nt][0];
        g_pacc[baseA * 128 + col + 1] = acc[nt][1];
        g_pacc[baseB * 128 + col]     = acc[nt][2];
        g_pacc[baseB * 128 + col + 1] = acc[nt][3];
    }
}

__global__ __launch_bounds__(128) void combine_kernel() {
    int bhs = blockIdx.x;
    int d = threadIdx.x;
    int base = bhs * NSPLIT;
    float m = -1e30f;
#pragma unroll
    for (int i = 0; i < NSPLIT; i++) m = fmaxf(m, g_pm[base + i]);
    float L = 0.f, o = 0.f;
#pragma unroll
    for (int i = 0; i < NSPLIT; i++) {
        float e = __expf(g_pm[base + i] - m);
        L += g_pl[base + i] * e;
        o += g_pacc[(base + i) * 128 + d] * e;
    }
    int b = bhs >> 9, h = (bhs >> 4) & 31, s = bhs & 15;
    g_attn[(b * 16 + s) * 4096 + h * 128 + d] = o / L;
}

// ============================================================
extern "C" void kernel_launch(void* const* d_in, const int* in_sizes, int n_in,
                              void* d_out, int out_size) {
    const float* x  = (const float*)d_in[0];
    const float* fc = (const float*)d_in[1];
    const float* fs = (const float*)d_in[2];
    const float* ck = (const float*)d_in[3];
    const float* cv = (const float*)d_in[4];
    const float* Wq = (const float*)d_in[5];
    const float* Wk = (const float*)d_in[6];
    const float* Wv = (const float*)d_in[7];
    const float* Wo = (const float*)d_in[8];
    float* out = (float*)d_out;

    cudaFuncSetAttribute(gemm_k<6144, false>, cudaFuncAttributeMaxDynamicSharedMemorySize, GEMM_SMEM);
    cudaFuncSetAttribute(gemm_k<4096, true>,  cudaFuncAttributeMaxDynamicSharedMemorySize, GEMM_SMEM);
    cudaFuncSetAttribute(attn_kernel, cudaFuncAttributeMaxDynamicSharedMemorySize, ATTN_SMEM);

    gemm_k<6144, false><<<dim3(48, KSPLIT), 256, GEMM_SMEM>>>(x, Wq, Wk, Wv);
    qkv_reduce<<<768, 256>>>(fc, fs);
    attn_kernel<<<dim3(NSPLIT, 8, 4), 128, ATTN_SMEM>>>(ck, cv);
    combine_kernel<<<2048, 128>>>();
    gemm_k<4096, true><<<dim3(32, KSPLIT), 256, GEMM_SMEM>>>(nullptr, Wo, nullptr, nullptr);
    out_reduce<<<256, 256>>>(out);
}

// round 3
// speedup vs baseline: 4.0565x; 1.2841x over previous
#include <cuda_runtime.h>
#include <cuda_bf16.h>
#include <cstdint>

#define DEV_INLINE __device__ __forceinline__

#define NSPLIT 9      // attention KV splits: 8 x 256 cached + 1 x 16 new
#define KSPLIT 8      // GEMM K splits
#define KCH    512    // K per split
#define BN     64     // N tile
#define ALD    36     // A smem ld (words)
#define BLD    72     // B smem ld (words)
#define STAGE_A (64 * ALD)
#define STAGE_B (32 * BLD)
#define STAGE_W (STAGE_A + STAGE_B)
#define GEMM_SMEM (3 * STAGE_W * 4)

// -------- device scratch (no allocations allowed) --------
__device__ float g_xq[64 * 4096];
__device__ float g_xk[64 * 1024];
__device__ float g_xv[64 * 1024];
__device__ float g_attn[64 * 4096];
__device__ float g_part[KSPLIT * 64 * 6144];
__device__ float g_pm[4 * 32 * 16 * NSPLIT];
__device__ float g_pl[4 * 32 * 16 * NSPLIT];
__device__ float g_pacc[4 * 32 * 16 * NSPLIT * 128];

DEV_INLINE uint32_t f2tf(float x) {
    uint32_t r; asm("cvt.rna.tf32.f32 %0, %1;" : "=r"(r) : "f"(x)); return r;
}
DEV_INLINE uint32_t smem_u32(const void* p) {
    uint32_t a;
    asm("{ .reg .u64 t; cvta.to.shared.u64 t, %1; cvt.u32.u64 %0, t; }" : "=r"(a) : "l"(p));
    return a;
}
DEV_INLINE void mma_tf32(float* c, const uint32_t* a, const uint32_t* b) {
    asm volatile(
        "mma.sync.aligned.m16n8k8.row.col.f32.tf32.tf32.f32 "
        "{%0,%1,%2,%3}, {%4,%5,%6,%7}, {%8,%9}, {%0,%1,%2,%3};\n"
        : "+f"(c[0]), "+f"(c[1]), "+f"(c[2]), "+f"(c[3])
        : "r"(a[0]), "r"(a[1]), "r"(a[2]), "r"(a[3]), "r"(b[0]), "r"(b[1]));
}
DEV_INLINE void cp16(uint32_t dst, const float* src) {
    asm volatile("cp.async.cg.shared.global [%0], [%1], 16;\n" :: "r"(dst), "l"(src));
}

// ============================================================
// Split-K GEMM: 64 x 64 tile per block, 128 threads, 3-stage cp.async
// ============================================================
template<int NTOT, bool AFA>
__global__ __launch_bounds__(128) void gemm_k(
    const float* __restrict__ Ain, const float* __restrict__ W0,
    const float* __restrict__ W1, const float* __restrict__ W2) {
    extern __shared__ float sm[];
    const int ntile = blockIdx.x, split = blockIdx.y;
    const int n0 = ntile * BN;
    const float* A = AFA ? (const float*)g_attn : Ain;
    const float* Bp; int ldn, nb;
    if (NTOT == 4096) { Bp = W0; ldn = 4096; nb = n0; }
    else {
        if (n0 < 4096)      { Bp = W0; ldn = 4096; nb = n0; }
        else if (n0 < 5120) { Bp = W1; ldn = 1024; nb = n0 - 4096; }
        else                { Bp = W2; ldn = 1024; nb = n0 - 5120; }
    }
    const int k0 = split * KCH;
    const int tid = threadIdx.x;
    const uint32_t sbase = smem_u32(sm);

    auto issue = [&](int it, int buf) {
        const int kc = k0 + it * 32;
        uint32_t as_ = sbase + buf * STAGE_W * 4;
        uint32_t bs_ = as_ + STAGE_A * 4;
#pragma unroll
        for (int i = 0; i < 4; i++) {                 // A: 64x32 = 512 float4
            int idx = tid + i * 128; int r = idx >> 3, c = (idx & 7) * 4;
            cp16(as_ + (r * ALD + c) * 4, A + r * 4096 + kc + c);
        }
#pragma unroll
        for (int i = 0; i < 4; i++) {                 // B: 32x64 = 512 float4
            int idx = tid + i * 128; int r = idx >> 4, c = (idx & 15) * 4;
            cp16(bs_ + (r * BLD + c) * 4, Bp + (kc + r) * ldn + nb + c);
        }
        asm volatile("cp.async.commit_group;\n");
    };

    const int w = tid >> 5, lane = tid & 31, g = lane >> 2, tg = lane & 3;
    const int mw = w * 16;

    float acc[8][4];
#pragma unroll
    for (int i = 0; i < 8; i++)
#pragma unroll
        for (int j = 0; j < 4; j++) acc[i][j] = 0.f;

    issue(0, 0); issue(1, 1);

    for (int it = 0; it < 16; it++) {
        __syncthreads();
        if (it + 2 < 16) issue(it + 2, (it + 2) % 3);
        else asm volatile("cp.async.commit_group;\n");
        asm volatile("cp.async.wait_group 2;\n");
        __syncthreads();
        const float* As = sm + (it % 3) * STAGE_W;
        const float* Bs = As + STAGE_A;
#pragma unroll
        for (int ks = 0; ks < 4; ks++) {
            const int kk = ks * 8;
            uint32_t a[4];
            a[0] = f2tf(As[(mw + g) * ALD + kk + tg]);
            a[1] = f2tf(As[(mw + g + 8) * ALD + kk + tg]);
            a[2] = f2tf(As[(mw + g) * ALD + kk + tg + 4]);
            a[3] = f2tf(As[(mw + g + 8) * ALD + kk + tg + 4]);
#pragma unroll
            for (int nt = 0; nt < 8; nt++) {
                uint32_t bb[2];
                bb[0] = f2tf(Bs[(kk + tg) * BLD + nt * 8 + g]);
                bb[1] = f2tf(Bs[(kk + tg + 4) * BLD + nt * 8 + g]);
                mma_tf32(acc[nt], a, bb);
            }
        }
    }

    float* outp = g_part + (size_t)split * 64 * NTOT;
#pragma unroll
    for (int nt = 0; nt < 8; nt++) {
        int col = n0 + nt * 8 + tg * 2;
        outp[(mw + g) * NTOT + col]         = acc[nt][0];
        outp[(mw + g) * NTOT + col + 1]     = acc[nt][1];
        outp[(mw + g + 8) * NTOT + col]     = acc[nt][2];
        outp[(mw + g + 8) * NTOT + col + 1] = acc[nt][3];
    }
}

// ============================================================
// qkv reduce + RoPE
// ============================================================
__global__ __launch_bounds__(256) void qkv_reduce(
    const float* __restrict__ fc, const float* __restrict__ fs) {
    int idx = blockIdx.x * 256 + threadIdx.x;
    int r = idx / 3072, p = idx % 3072;
    int n = p * 2;
    float v0 = 0.f, v1 = 0.f;
#pragma unroll
    for (int s = 0; s < 8; s++) {
        float2 vv = *(const float2*)(g_part + ((size_t)s * 64 + r) * 6144 + n);
        v0 += vv.x; v1 += vv.y;
    }
    int srow = r & 15;
    if (n < 4096) {
        int i2 = (n & 127) >> 1;
        float c = fc[srow * 64 + i2], sn = fs[srow * 64 + i2];
        g_xq[r * 4096 + n]     = v0 * c - v1 * sn;
        g_xq[r * 4096 + n + 1] = v0 * sn + v1 * c;
    } else if (n < 5120) {
        int nk = n - 4096; int i2 = (nk & 127) >> 1;
        float c = fc[srow * 64 + i2], sn = fs[srow * 64 + i2];
        g_xk[r * 1024 + nk]     = v0 * c - v1 * sn;
        g_xk[r * 1024 + nk + 1] = v0 * sn + v1 * c;
    } else {
        int nv = n - 5120;
        g_xv[r * 1024 + nv]     = v0;
        g_xv[r * 1024 + nv + 1] = v1;
    }
}

__global__ __launch_bounds__(256) void out_reduce(float* __restrict__ out) {
    int idx = blockIdx.x * 256 + threadIdx.x;
    float4 acc = make_float4(0.f, 0.f, 0.f, 0.f);
#pragma unroll
    for (int s = 0; s < 8; s++) {
        float4 v = *(const float4*)(g_part + (size_t)s * 64 * 4096 + idx * 4);
        acc.x += v.x; acc.y += v.y; acc.z += v.z; acc.w += v.w;
    }
    *(float4*)(out + idx * 4) = acc;
}

// ============================================================
// split-KV flash attention: 32-key chunks, double-buffered cp.async
// ============================================================
#define QLD 132
#define KLD 132
#define VLD 136
#define PLD 36
#define AQ_W  (64 * QLD)
#define AK_W  (32 * KLD)
#define AV_W  (32 * VLD)
#define AP_W  (64 * PLD)
#define ATTN_SMEM ((AQ_W + 2 * AK_W + 2 * AV_W + AP_W) * 4)

__global__ __launch_bounds__(128) void attn_kernel(
    const float* __restrict__ cache_k, const float* __restrict__ cache_v) {
    extern __shared__ float smf[];
    uint32_t* Qs = (uint32_t*)smf;                    // tf32
    float* Kb = smf + AQ_W;                           // 2 x 32 x KLD (f32)
    float* Vb = Kb + 2 * AK_W;                        // 2 x 32 x VLD (f32)
    uint32_t* Ps = (uint32_t*)(Vb + 2 * AV_W);        // tf32

    const int split = blockIdx.x, kvh = blockIdx.y, b = blockIdx.z;
    const int tid = threadIdx.x, w = tid >> 5, lane = tid & 31;
    const int g = lane >> 2, tg = lane & 3;
    const uint32_t sbase = smem_u32(smf);
    const uint32_t kbase = sbase + AQ_W * 4;
    const uint32_t vbase = kbase + 2 * AK_W * 4;
    const int nch = (split < 8) ? 8 : 1;

    auto issue = [&](int ch, int buf) {
        uint32_t kb = kbase + buf * AK_W * 4;
        uint32_t vb = vbase + buf * AV_W * 4;
        if (split < 8) {
#pragma unroll
            for (int i = 0; i < 8; i++) {
                int idx = tid + i * 128; int jk = idx >> 5, c = (idx & 31) * 4;
                int j = split * 256 + ch * 32 + jk;
                int off = ((b * 4096 + j) * 8 + kvh) * 128 + c;
                cp16(kb + (jk * KLD + c) * 4, cache_k + off);
                cp16(vb + (jk * VLD + c) * 4, cache_v + off);
            }
        } else {
#pragma unroll
            for (int i = 0; i < 4; i++) {             // only 16 new keys
                int idx = tid + i * 128; int jk = idx >> 5, c = (idx & 31) * 4;
                int off = (b * 16 + jk) * 1024 + kvh * 128 + c;
                cp16(kb + (jk * KLD + c) * 4, g_xk + off);
                cp16(vb + (jk * VLD + c) * 4, g_xv + off);
            }
        }
        asm volatile("cp.async.commit_group;\n");
    };

    // zero pad rows 16..31 for the new-key split (before issuing)
    if (split == 8) {
#pragma unroll
        for (int i = 0; i < 16; i++) {
            int idx = tid + i * 128; int jk = 16 + (idx >> 5), c = idx & 31;
            Kb[jk * KLD + c * 4] = 0.f; Kb[jk * KLD + c * 4 + 1] = 0.f;
            Kb[jk * KLD + c * 4 + 2] = 0.f; Kb[jk * KLD + c * 4 + 3] = 0.f;
            Vb[jk * VLD + c * 4] = 0.f; Vb[jk * VLD + c * 4 + 1] = 0.f;
            Vb[jk * VLD + c * 4 + 2] = 0.f; Vb[jk * VLD + c * 4 + 3] = 0.f;
        }
    }
    issue(0, 0);

    // Load Q tile [64 x 128] -> tf32 (overlaps chunk-0 cp.async)
#pragma unroll
    for (int i = 0; i < 16; i++) {
        int idx = tid + i * 128; int r = idx >> 5, c = (idx & 31) * 4;
        int hig = r >> 4, s = r & 15;
        float4 v = *(const float4*)(g_xq + (b * 16 + s) * 4096 + (kvh * 4 + hig) * 128 + c);
        uint32_t* q = &Qs[r * QLD + c];
        q[0] = f2tf(v.x); q[1] = f2tf(v.y); q[2] = f2tf(v.z); q[3] = f2tf(v.w);
    }

    float acc[16][4];
#pragma unroll
    for (int i = 0; i < 16; i++)
#pragma unroll
        for (int j = 0; j < 4; j++) acc[i][j] = 0.f;
    float m0 = -1e30f, m1 = -1e30f, l0 = 0.f, l1 = 0.f;
    const float scale = 0.08838834764831845f;

    for (int ch = 0; ch < nch; ch++) {
        if (ch + 1 < nch) {
            issue(ch + 1, (ch + 1) & 1);
            asm volatile("cp.async.wait_group 1;\n");
        } else {
            asm volatile("cp.async.wait_group 0;\n");
        }
        __syncthreads();
        const float* Kc = Kb + (ch & 1) * AK_W;
        const float* Vc = Vb + (ch & 1) * AV_W;

        // GEMM1: S[16 x 32] per warp
        float sc[4][4];
#pragma unroll
        for (int i = 0; i < 4; i++)
#pragma unroll
            for (int j = 0; j < 4; j++) sc[i][j] = 0.f;
#pragma unroll
        for (int ks = 0; ks < 16; ks++) {
            uint32_t a[4];
            a[0] = Qs[(w * 16 + g) * QLD + ks * 8 + tg];
            a[1] = Qs[(w * 16 + g + 8) * QLD + ks * 8 + tg];
            a[2] = Qs[(w * 16 + g) * QLD + ks * 8 + tg + 4];
            a[3] = Qs[(w * 16 + g + 8) * QLD + ks * 8 + tg + 4];
#pragma unroll
            for (int nt = 0; nt < 4; nt++) {
                uint32_t bb[2];
                bb[0] = f2tf(Kc[(nt * 8 + g) * KLD + ks * 8 + tg]);
                bb[1] = f2tf(Kc[(nt * 8 + g) * KLD + ks * 8 + tg + 4]);
                mma_tf32(sc[nt], a, bb);
            }
        }

        // online softmax
        float mx0 = -1e30f, mx1 = -1e30f;
#pragma unroll
        for (int nt = 0; nt < 4; nt++) {
#pragma unroll
            for (int r = 0; r < 4; r++) {
                float v = sc[nt][r] * scale;
                if (split == 8) {
                    int key = nt * 8 + tg * 2 + (r & 1);
                    if (key >= 16) v = -1e30f;
                }
                sc[nt][r] = v;
            }
            mx0 = fmaxf(mx0, fmaxf(sc[nt][0], sc[nt][1]));
            mx1 = fmaxf(mx1, fmaxf(sc[nt][2], sc[nt][3]));
        }
        mx0 = fmaxf(mx0, __shfl_xor_sync(0xffffffffu, mx0, 1));
        mx0 = fmaxf(mx0, __shfl_xor_sync(0xffffffffu, mx0, 2));
        mx1 = fmaxf(mx1, __shfl_xor_sync(0xffffffffu, mx1, 1));
        mx1 = fmaxf(mx1, __shfl_xor_sync(0xffffffffu, mx1, 2));
        float nm0 = fmaxf(m0, mx0), nm1 = fmaxf(m1, mx1);
        float f0 = __expf(m0 - nm0), f1 = __expf(m1 - nm1);
        float s0 = 0.f, s1 = 0.f;
#pragma unroll
        for (int nt = 0; nt < 4; nt++) {
            float p0 = __expf(sc[nt][0] - nm0), p1 = __expf(sc[nt][1] - nm0);
            float p2 = __expf(sc[nt][2] - nm1), p3 = __expf(sc[nt][3] - nm1);
            s0 += p0 + p1; s1 += p2 + p3;
            uint32_t* pr  = &Ps[(w * 16 + g) * PLD + nt * 8 + tg * 2];
            pr[0] = f2tf(p0); pr[1] = f2tf(p1);
            uint32_t* pr2 = &Ps[(w * 16 + g + 8) * PLD + nt * 8 + tg * 2];
            pr2[0] = f2tf(p2); pr2[1] = f2tf(p3);
        }
        s0 += __shfl_xor_sync(0xffffffffu, s0, 1);
        s0 += __shfl_xor_sync(0xffffffffu, s0, 2);
        s1 += __shfl_xor_sync(0xffffffffu, s1, 1);
        s1 += __shfl_xor_sync(0xffffffffu, s1, 2);
        l0 = l0 * f0 + s0; l1 = l1 * f1 + s1;
        m0 = nm0; m1 = nm1;
#pragma unroll
        for (int nt = 0; nt < 16; nt++) {
            acc[nt][0] *= f0; acc[nt][1] *= f0;
            acc[nt][2] *= f1; acc[nt][3] *= f1;
        }
        __syncwarp();

        // GEMM2: acc += P @ V  (contraction over 32 keys)
#pragma unroll
        for (int k2 = 0; k2 < 4; k2++) {
            uint32_t a[4];
            a[0] = Ps[(w * 16 + g) * PLD + k2 * 8 + tg];
            a[1] = Ps[(w * 16 + g + 8) * PLD + k2 * 8 + tg];
            a[2] = Ps[(w * 16 + g) * PLD + k2 * 8 + tg + 4];
            a[3] = Ps[(w * 16 + g + 8) * PLD + k2 * 8 + tg + 4];
#pragma unroll
            for (int nt = 0; nt < 16; nt++) {
                uint32_t bb[2];
                bb[0] = f2tf(Vc[(k2 * 8 + tg) * VLD + nt * 8 + g]);
                bb[1] = f2tf(Vc[(k2 * 8 + tg + 4) * VLD + nt * 8 + g]);
                mma_tf32(acc[nt], a, bb);
            }
        }
        __syncthreads();
    }

    const int h = kvh * 4 + w;
    const int baseA = ((b * 32 + h) * 16 + g) * NSPLIT + split;
    const int baseB = ((b * 32 + h) * 16 + g + 8) * NSPLIT + split;
    if (tg == 0) {
        g_pm[baseA] = m0; g_pl[baseA] = l0;
        g_pm[baseB] = m1; g_pl[baseB] = l1;
    }
#pragma unroll
    for (int nt = 0; nt < 16; nt++) {
        int col = nt * 8 + tg * 2;
        g_pacc[baseA * 128 + col]     = acc[nt][0];
        g_pacc[baseA * 128 + col + 1] = acc[nt][1];
        g_pacc[baseB * 128 + col]     = acc[nt][2];
        g_pacc[baseB * 128 + col + 1] = acc[nt][3];
    }
}

// ============================================================
// combine: float4 loads, 4 rows per block
// ============================================================
__global__ __launch_bounds__(128) void combine_kernel() {
    int bhs = blockIdx.x * 4 + (threadIdx.x >> 5);
    int lane = threadIdx.x & 31;
    int base = bhs * NSPLIT;
    float m = -1e30f;
#pragma unroll
    for (int i = 0; i < NSPLIT; i++) m = fmaxf(m, g_pm[base + i]);
    float L = 0.f;
    float4 o = make_float4(0.f, 0.f, 0.f, 0.f);
#pragma unroll
    for (int i = 0; i < NSPLIT; i++) {
        float e = __expf(g_pm[base + i] - m);
        L += g_pl[base + i] * e;
        float4 v = *(const float4*)(g_pacc + (base + i) * 128 + lane * 4);
        o.x += v.x * e; o.y += v.y * e; o.z += v.z * e; o.w += v.w * e;
    }
    float inv = 1.f / L;
    int b = bhs >> 9, h = (bhs >> 4) & 31, s = bhs & 15;
    float4 r = make_float4(o.x * inv, o.y * inv, o.z * inv, o.w * inv);
    *(float4*)(g_attn + (b * 16 + s) * 4096 + h * 128 + lane * 4) = r;
}

// ============================================================
extern "C" void kernel_launch(void* const* d_in, const int* in_sizes, int n_in,
                              void* d_out, int out_size) {
    const float* x  = (const float*)d_in[0];
    const float* fc = (const float*)d_in[1];
    const float* fs = (const float*)d_in[2];
    const float* ck = (const float*)d_in[3];
    const float* cv = (const float*)d_in[4];
    const float* Wq = (const float*)d_in[5];
    const float* Wk = (const float*)d_in[6];
    const float* Wv = (const float*)d_in[7];
    const float* Wo = (const float*)d_in[8];
    float* out = (float*)d_out;

    cudaFuncSetAttribute(gemm_k<6144, false>, cudaFuncAttributeMaxDynamicSharedMemorySize, GEMM_SMEM);
    cudaFuncSetAttribute(gemm_k<4096, true>,  cudaFuncAttributeMaxDynamicSharedMemorySize, GEMM_SMEM);
    cudaFuncSetAttribute(attn_kernel, cudaFuncAttributeMaxDynamicSharedMemorySize, ATTN_SMEM);

    gemm_k<6144, false><<<dim3(96, KSPLIT), 128, GEMM_SMEM>>>(x, Wq, Wk, Wv);
    qkv_reduce<<<768, 256>>>(fc, fs);
    attn_kernel<<<dim3(NSPLIT, 8, 4), 128, ATTN_SMEM>>>(ck, cv);
    combine_kernel<<<512, 128>>>();
    gemm_k<4096, true><<<dim3(64, KSPLIT), 128, GEMM_SMEM>>>(nullptr, Wo, nullptr, nullptr);
    out_reduce<<<256, 256>>>(out);
}